// round 11
// baseline (speedup 1.0000x reference)
#include <cuda_runtime.h>
#include <cuda_fp16.h>
#include <math.h>
#include <stdint.h>

// Problem constants
#define Bz 64
#define Lz 512
#define Iz 256
#define Hz 512
#define Gz 2048           // 4*H
#define Mz (Lz*Bz)        // 32768
#define NCD 64            // CTAs per direction in the recurrence kernel

// ---------------- scratch (device globals: allocation-free) ----------------
__device__ float g_xg[(size_t)2 * Mz * Gz];          // per-dir precomputed input gates (fp32)
__device__ __half g_hf[2 * Bz * Hz];                 // running h per direction (fp16)
__device__ unsigned g_cnt1[2][8][32];                // leaf counters (8/dir, 128B apart)
__device__ unsigned g_cnt2[2][32];                   // root counters (128B apart)
__device__ unsigned g_gen[2][32];                    // generation words (128B apart)
__device__ __half g_Af [(size_t)Mz * 1024];          // fp16 activations (layer input, m = t*B+b)
__device__ __half g_Whf[(size_t)2 * Gz * 1024];      // fp16 Wih hi
__device__ __half g_Wlf[(size_t)2 * Gz * 1024];      // fp16 Wih lo

// ======================= PTX helpers (base-ISA only) =======================
__device__ __forceinline__ uint32_t smem_to_u32(const void* p) {
    uint32_t a;
    asm("{ .reg .u64 t; cvta.to.shared.u64 t, %1; cvt.u32.u64 %0, t; }" : "=r"(a) : "l"(p));
    return a;
}
__device__ __forceinline__ void cpa16(uint32_t s, const void* g) {
    asm volatile("cp.async.cg.shared.global [%0], [%1], 16;" :: "r"(s), "l"(g));
}
__device__ __forceinline__ void ldsm_x4(uint32_t& r0, uint32_t& r1, uint32_t& r2, uint32_t& r3,
                                        uint32_t a) {
    asm volatile("ldmatrix.sync.aligned.m8n8.x4.shared.b16 {%0,%1,%2,%3}, [%4];"
                 : "=r"(r0), "=r"(r1), "=r"(r2), "=r"(r3) : "r"(a));
}
__device__ __forceinline__ void mma16816h(float* d, const uint32_t* a, const uint32_t* b) {
    asm volatile("mma.sync.aligned.m16n8k16.row.col.f32.f16.f16.f32 "
                 "{%0,%1,%2,%3}, {%4,%5,%6,%7}, {%8,%9}, {%0,%1,%2,%3};"
                 : "+f"(d[0]), "+f"(d[1]), "+f"(d[2]), "+f"(d[3])
                 : "r"(a[0]), "r"(a[1]), "r"(a[2]), "r"(a[3]), "r"(b[0]), "r"(b[1]));
}
// fast sigmoid (tanh stays exact)
__device__ __forceinline__ float sigf(float x) {
    return __fdividef(1.f, 1.f + __expf(-x));
}

// ============================================================================
// Conversion kernels (layer-0 inputs only; layer-1 A is written by recurrence)
// ============================================================================
__global__ void conv_A_f16(const float* __restrict__ src)
{
    // x: [b][t][k] (K=256) -> g_Af[m= t*64+b][k]
    const size_t i = ((size_t)blockIdx.x * 256 + threadIdx.x) * 4;
    const size_t m = i >> 8;
    const size_t k = i & 255;
    const float4 v = *((const float4*)(src + ((m & 63) * 512 + (m >> 6)) * 256 + k));
    *((__half2*)(g_Af + i))     = __floats2half2_rn(v.x, v.y);
    *((__half2*)(g_Af + i + 2)) = __floats2half2_rn(v.z, v.w);
}

__global__ void conv_W_f16(const float* __restrict__ Wf, const float* __restrict__ Wr, int K)
{
    const int dir = blockIdx.y;
    const size_t i = ((size_t)blockIdx.x * 256 + threadIdx.x) * 4;   // over 2048*K
    const float* src = dir ? Wr : Wf;
    const size_t off = (size_t)dir * Gz * K;
    const float4 v = *((const float4*)(src + i));
    __half h0 = __float2half_rn(v.x), h1 = __float2half_rn(v.y);
    __half h2 = __float2half_rn(v.z), h3 = __float2half_rn(v.w);
    __half l0 = __float2half_rn(v.x - __half2float(h0));
    __half l1 = __float2half_rn(v.y - __half2float(h1));
    __half l2 = __float2half_rn(v.z - __half2float(h2));
    __half l3 = __float2half_rn(v.w - __half2float(h3));
    *((__half2*)(g_Whf + off + i))     = __halves2half2(h0, h1);
    *((__half2*)(g_Whf + off + i + 2)) = __halves2half2(h2, h3);
    *((__half2*)(g_Wlf + off + i))     = __halves2half2(l0, l1);
    *((__half2*)(g_Wlf + off + i + 2)) = __halves2half2(l2, l3);
}

// ============================================================================
// mma.sync GEMM: Xg = bias + A @ W^T.  A fp16 single; W fp16 hi (+lo if terms=2).
// CTA 128x128, BK=32, 8 warps (2Mx4N), 3-stage cp.async, 2 CTAs/SM.
// smem rows padded to 80B -> conflict-free ldmatrix.
// ============================================================================
#define TAH 0
#define TBH 10240
#define TBL 20480
#define BUFB 30720
#define GEMM_SMEM (3*BUFB)

__global__ void __launch_bounds__(256, 2) gates_gemm_mma(
    const float* __restrict__ bi_f, const float* __restrict__ bh_f,
    const float* __restrict__ bi_r, const float* __restrict__ bh_r, int K, int terms)
{
    extern __shared__ char smem[];
    const uint32_t sb = smem_to_u32(smem);
    __shared__ float sBias[128];

    const int tid = threadIdx.x;
    const int wid = tid >> 5;
    const int lane = tid & 31;
    const int warpM = wid >> 2;       // 0..1
    const int warpN = wid & 3;        // 0..3
    const int dir = blockIdx.z;
    const int n0 = blockIdx.x * 128;
    const int m0 = blockIdx.y * 128;

    const __half* __restrict__ Wh = g_Whf + (size_t)dir * Gz * K;
    const __half* __restrict__ Wl = g_Wlf + (size_t)dir * Gz * K;
    const float* bi = dir ? bi_r : bi_f;
    const float* bh = dir ? bh_r : bh_f;
    if (tid < 128) sBias[tid] = bi[n0 + tid] + bh[n0 + tid];

    float acc[4][4][4];
#pragma unroll
    for (int mt = 0; mt < 4; mt++)
#pragma unroll
        for (int nt = 0; nt < 4; nt++)
#pragma unroll
            for (int q = 0; q < 4; q++) acc[mt][nt][q] = 0.f;

    const int lrow = tid >> 2;
    const int lseg = tid & 3;

#define LOAD_CHUNK(kc, boff) do { \
    _Pragma("unroll") \
    for (int i = 0; i < 2; i++) { \
        const int row = lrow + 64 * i; \
        const uint32_t so = (uint32_t)(row * 80 + lseg * 16); \
        const size_t ga = (size_t)(m0 + row) * K + (kc) + lseg * 8; \
        const size_t gb = (size_t)(n0 + row) * K + (kc) + lseg * 8; \
        cpa16(sb + (boff) + TAH + so, g_Af + ga); \
        cpa16(sb + (boff) + TBH + so, Wh + gb); \
        if (terms == 2) cpa16(sb + (boff) + TBL + so, Wl + gb); \
    } \
    asm volatile("cp.async.commit_group;" ::: "memory"); \
} while (0)

    const int nch = K >> 5;
    LOAD_CHUNK(0, 0);
    LOAD_CHUNK(32, BUFB);

    const int aRowOff = (lane & 7) + ((lane >> 3) & 1) * 8;
    const int aColOff = ((lane >> 4) & 1) * 16;
    const int bRowOff = (lane & 7) + ((lane >> 4) & 1) * 8;
    const int bColOff = ((lane >> 3) & 1) * 16;

    int buf = 0;
    for (int ch = 0; ch < nch; ch++) {
        if (ch + 1 < nch) asm volatile("cp.async.wait_group 1;" ::: "memory");
        else              asm volatile("cp.async.wait_group 0;" ::: "memory");
        __syncthreads();

        const uint32_t boff = sb + (uint32_t)(buf * BUFB);
#pragma unroll
        for (int ks = 0; ks < 2; ks++) {
            const int kb = ks * 32;
            uint32_t aH[4][4], bH[4][2];
#pragma unroll
            for (int mt = 0; mt < 4; mt++) {
                const uint32_t ra = (uint32_t)((warpM * 64 + mt * 16 + aRowOff) * 80 + kb + aColOff);
                ldsm_x4(aH[mt][0], aH[mt][1], aH[mt][2], aH[mt][3], boff + TAH + ra);
            }
#pragma unroll
            for (int p = 0; p < 2; p++) {
                const uint32_t rb = (uint32_t)((warpN * 32 + p * 16 + bRowOff) * 80 + kb + bColOff);
                uint32_t r0, r1, r2, r3;
                ldsm_x4(r0, r1, r2, r3, boff + TBH + rb);
                bH[2*p][0] = r0; bH[2*p][1] = r1; bH[2*p+1][0] = r2; bH[2*p+1][1] = r3;
            }
#pragma unroll
            for (int mt = 0; mt < 4; mt++)
#pragma unroll
                for (int nt = 0; nt < 4; nt++)
                    mma16816h(acc[mt][nt], aH[mt], bH[nt]);
            if (terms == 2) {
                uint32_t bL[4][2];
#pragma unroll
                for (int p = 0; p < 2; p++) {
                    const uint32_t rb = (uint32_t)((warpN * 32 + p * 16 + bRowOff) * 80 + kb + bColOff);
                    uint32_t r0, r1, r2, r3;
                    ldsm_x4(r0, r1, r2, r3, boff + TBL + rb);
                    bL[2*p][0] = r0; bL[2*p][1] = r1; bL[2*p+1][0] = r2; bL[2*p+1][1] = r3;
                }
#pragma unroll
                for (int mt = 0; mt < 4; mt++)
#pragma unroll
                    for (int nt = 0; nt < 4; nt++)
                        mma16816h(acc[mt][nt], aH[mt], bL[nt]);
            }
        }
        if (ch + 2 < nch) {
            const int nb = (buf + 2) % 3;
            LOAD_CHUNK((ch + 2) << 5, (uint32_t)(nb * BUFB));
        }
        buf = (buf + 1) % 3;
    }

    float* __restrict__ outp = g_xg + (size_t)dir * Mz * Gz;
    const int g  = lane >> 2;
    const int tg = lane & 3;
#pragma unroll
    for (int mt = 0; mt < 4; mt++) {
        const int m = m0 + warpM * 64 + mt * 16 + g;
#pragma unroll
        for (int nt = 0; nt < 4; nt++) {
            const int nl = warpN * 32 + nt * 8 + tg * 2;
            const float b0 = sBias[nl], b1 = sBias[nl + 1];
            float2 v0 = make_float2(acc[mt][nt][0] + b0, acc[mt][nt][1] + b1);
            float2 v1 = make_float2(acc[mt][nt][2] + b0, acc[mt][nt][3] + b1);
            *((float2*)(outp + (size_t)m * Gz + n0 + nl)) = v0;
            *((float2*)(outp + (size_t)(m + 8) * Gz + n0 + nl)) = v1;
        }
    }
#undef LOAD_CHUNK
}

// ============================================================================
// Persistent recurrence: TWO-LEVEL atomic grid barrier (8x8 tree; same proven
// atomic RMW primitives as R8, lower same-address serialization);
// W-frags in registers; layer-0 writes fp16 g_Af directly; layer-1 -> dout.
// 128 CTAs (64/dir), 256 thr. CTA cb owns h-cols [cb*8,cb*8+8) -> 32 gate cols.
// ============================================================================
__device__ __forceinline__ void grid_bar(int dir, int cb, unsigned target)
{
    __syncthreads();
    if (threadIdx.x == 0) {
        __threadfence();
        const int grp = cb >> 3;
        const unsigned p1 = atomicAdd(&g_cnt1[dir][grp][0], 1u);
        if (p1 == 7u) {                           // leaf leader
            atomicExch(&g_cnt1[dir][grp][0], 0u);
            const unsigned p2 = atomicAdd(&g_cnt2[dir][0], 1u);
            if (p2 == 7u) {                       // root leader
                atomicExch(&g_cnt2[dir][0], 0u);
                __threadfence();
                atomicExch(&g_gen[dir][0], target);
            }
        }
        while (*((volatile unsigned*)&g_gen[dir][0]) != target) { }
        __threadfence();
    }
    __syncthreads();
}

// dynamic smem layout (bytes)
#define RP 1040                   // row pitch: 520 halfs (512 + 8 pad)
#define SWH  0                    // [32][520] fp16   33280 B (init staging only)
#define SAH  33280                // [64][520] fp16   66560 B
#define SXG  99840                // 2 x [64][36] fp32  18432 B
#define XGB  9216                 // xg buffer stride
#define SGT  118272               // [64][34] fp32     8704 B
#define REC_SMEM 126976

__global__ void __launch_bounds__(256) lstm_recur_mma(
    const float* __restrict__ Whh_f, const float* __restrict__ Whh_r,
    float* __restrict__ dout, int layer)
{
    extern __shared__ char dsm[];
    const uint32_t sb = smem_to_u32(dsm);
    __shared__ unsigned s_base;

    const int dir = (int)(blockIdx.x) / NCD;
    const int cb  = (int)(blockIdx.x) % NCD;
    const float* __restrict__ W  = dir ? Whh_r : Whh_f;
    const float* __restrict__ xg = g_xg + (size_t)dir * Mz * Gz;
    __half* hb = g_hf + dir * Bz * Hz;

    const int tid = threadIdx.x;
    const int wid = tid >> 5;
    const int lane = tid & 31;
    const int warpM = wid & 3;        // 4 warps over M=64 (16 rows each)
    const int warpN = wid >> 2;       // 2 warps over N=32 (16 cols each)

    if (tid == 0) s_base = *((volatile unsigned*)&g_gen[dir][0]);

    // ---- stage Whh slice -> fp16 smem (one time), then lift to registers ----
    __half* sW = (__half*)(dsm + SWH);
#pragma unroll
    for (int i = 0; i < 16; i++) {
        const int idx = tid + 256 * i;       // 0..4095 over 32 rows x 128 float4
        const int n  = idx >> 7;             // local gate col 0..31
        const int f4 = idx & 127;
        const int gcol = (n >> 3) * Hz + cb * 8 + (n & 7);
        const float4 v = *((const float4*)(W + (size_t)gcol * Hz + f4 * 4));
        __half* ph = sW + n * 520 + f4 * 4;
        ph[0] = __float2half_rn(v.x); ph[1] = __float2half_rn(v.y);
        ph[2] = __float2half_rn(v.z); ph[3] = __float2half_rn(v.w);
    }

    // zero-init owned h columns (fp16)
#pragma unroll
    for (int r = 0; r < 2; r++) {
        const int id = tid + 256 * r;
        hb[(id >> 3) * Hz + cb * 8 + (id & 7)] = __float2half(0.f);
    }
    __syncthreads();

    const int aRowOff = (lane & 7) + ((lane >> 3) & 1) * 8;
    const int aColOff = ((lane >> 4) & 1) * 16;
    const int bRowOff = (lane & 7) + ((lane >> 4) & 1) * 8;
    const int bColOff = ((lane >> 3) & 1) * 16;

    // W fragments -> registers (step-invariant): 32 ks x 4 regs
    uint32_t bw[32][4];
    {
        const uint32_t bBase = sb + SWH + (uint32_t)((warpN * 16 + bRowOff) * RP + bColOff);
#pragma unroll
        for (int ks = 0; ks < 32; ks++)
            ldsm_x4(bw[ks][0], bw[ks][1], bw[ks][2], bw[ks][3], bBase + ks * 32);
    }

    const unsigned base = s_base;
    unsigned bar = 0;
    float creg[2] = {0.f, 0.f};
    grid_bar(dir, cb, base + (++bar));   // h=0 visible everywhere

    float* sGf = (float*)(dsm + SGT);   // [64][34]

#define XG_LOAD(t_, buf_) do { \
    _Pragma("unroll") \
    for (int i = 0; i < 2; i++) { \
        const int idx = tid + 256 * i; \
        const int b = idx >> 3, rem = idx & 7; \
        const int g = rem >> 1, q = rem & 1; \
        cpa16(sb + SXG + (buf_) * XGB + b * 144 + g * 32 + q * 16, \
              xg + ((size_t)(t_) * Bz + b) * Gz + g * Hz + cb * 8 + q * 4); \
    } \
    asm volatile("cp.async.commit_group;" ::: "memory"); \
} while (0)
#define H_LOAD(c0_) do { \
    _Pragma("unroll") \
    for (int i = 0; i < 8; i++) { \
        const int idx = tid + 256 * i;   /* 0..2047 */ \
        const int b = idx >> 5, seg = (idx & 31) + (c0_) * 32; \
        cpa16(sb + SAH + b * RP + seg * 16, hb + b * Hz + seg * 8); \
    } \
    asm volatile("cp.async.commit_group;" ::: "memory"); \
} while (0)

    // prologue: xg for step 0 into buffer 0
    {
        const int t0 = dir ? (Lz - 1) : 0;
        XG_LOAD(t0, 0);
    }

    for (int s = 0; s < Lz; s++) {
        const int t = dir ? (Lz - 1 - s) : s;

        H_LOAD(0);
        H_LOAD(1);
        if (s + 1 < Lz) {
            const int tn = dir ? (Lz - 2 - s) : (s + 1);
            XG_LOAD(tn, (s + 1) & 1);
        }

        const uint32_t aBase = sb + SAH + (uint32_t)((warpM * 16 + aRowOff) * RP + aColOff);
        float acc0[4] = {0.f,0.f,0.f,0.f};
        float acc1[4] = {0.f,0.f,0.f,0.f};

        asm volatile("cp.async.wait_group 2;" ::: "memory");
        __syncthreads();
#pragma unroll
        for (int ks = 0; ks < 16; ks++) {
            uint32_t a[4];
            ldsm_x4(a[0], a[1], a[2], a[3], aBase + ks * 32);
            mma16816h(acc0, a, bw[ks]);
            mma16816h(acc1, a, bw[ks] + 2);
        }
        if (s + 1 < Lz) asm volatile("cp.async.wait_group 1;" ::: "memory");
        else            asm volatile("cp.async.wait_group 0;" ::: "memory");
        __syncthreads();
#pragma unroll
        for (int ks = 16; ks < 32; ks++) {
            uint32_t a[4];
            ldsm_x4(a[0], a[1], a[2], a[3], aBase + ks * 32);
            mma16816h(acc0, a, bw[ks]);
            mma16816h(acc1, a, bw[ks] + 2);
        }

        // ---- write frags to sG ----
        {
            const int g = lane >> 2, tg = lane & 3;
            const int r = warpM * 16 + g;
            const int c = warpN * 16 + tg * 2;
            *((float2*)(sGf + r * 34 + c))           = make_float2(acc0[0], acc0[1]);
            *((float2*)(sGf + (r + 8) * 34 + c))     = make_float2(acc0[2], acc0[3]);
            *((float2*)(sGf + r * 34 + c + 8))       = make_float2(acc1[0], acc1[1]);
            *((float2*)(sGf + (r + 8) * 34 + c + 8)) = make_float2(acc1[2], acc1[3]);
        }
        __syncthreads();

        // ---- elementwise LSTM cell (fast sigmoid, exact tanh) ----
        const float* sXGf = (const float*)(dsm + SXG + (s & 1) * XGB);
#pragma unroll
        for (int r = 0; r < 2; r++) {
            const int id = tid + 256 * r;
            const int b = id >> 3, j = id & 7;
            const float iv = sGf[b*34 + j]      + sXGf[b*36 + j];
            const float fv = sGf[b*34 + 8 + j]  + sXGf[b*36 + 8 + j];
            const float gv = sGf[b*34 + 16 + j] + sXGf[b*36 + 16 + j];
            const float ov = sGf[b*34 + 24 + j] + sXGf[b*36 + 24 + j];
            const float c  = sigf(fv)*creg[r] + sigf(iv)*tanhf(gv);
            const float hv = sigf(ov)*tanhf(c);
            creg[r] = c;
            const int hcol = cb*8 + j;
            const __half hvh = __float2half(hv);
            hb[b*Hz + hcol] = hvh;
            if (layer) {
                dout[(size_t)b*(Lz*2*Hz) + (size_t)t*(2*Hz) + dir*Hz + hcol] = hv;
            } else {
                g_Af[((size_t)t*Bz + b)*1024 + dir*Hz + hcol] = hvh;
            }
        }
        grid_bar(dir, cb, base + (++bar));
    }
#undef XG_LOAD
#undef H_LOAD
}

// ============================================================================
// Launch sequence (graph-capturable, allocation-free)
// ============================================================================
extern "C" void kernel_launch(void* const* d_in, const int* in_sizes, int n_in,
                              void* d_out, int out_size)
{
    const float* x      = (const float*)d_in[0];
    const float* Wih_f0 = (const float*)d_in[1];
    const float* Whh_f0 = (const float*)d_in[2];
    const float* bih_f0 = (const float*)d_in[3];
    const float* bhh_f0 = (const float*)d_in[4];
    const float* Wih_r0 = (const float*)d_in[5];
    const float* Whh_r0 = (const float*)d_in[6];
    const float* bih_r0 = (const float*)d_in[7];
    const float* bhh_r0 = (const float*)d_in[8];
    const float* Wih_f1 = (const float*)d_in[9];
    const float* Whh_f1 = (const float*)d_in[10];
    const float* bih_f1 = (const float*)d_in[11];
    const float* bhh_f1 = (const float*)d_in[12];
    const float* Wih_r1 = (const float*)d_in[13];
    const float* Whh_r1 = (const float*)d_in[14];
    const float* bih_r1 = (const float*)d_in[15];
    const float* bhh_r1 = (const float*)d_in[16];
    float* outp = (float*)d_out;

    cudaFuncSetAttribute(gates_gemm_mma, cudaFuncAttributeMaxDynamicSharedMemorySize, GEMM_SMEM);
    cudaFuncSetAttribute(lstm_recur_mma, cudaFuncAttributeMaxDynamicSharedMemorySize, REC_SMEM);

    const dim3 gemm_grid(Gz/128, Mz/128, 2);     // (16, 256, 2)

    // ---- layer 0 (K = 256, 1-term W) ----
    conv_W_f16<<<dim3((Gz*256)/1024, 2), 256>>>(Wih_f0, Wih_r0, 256);
    conv_A_f16<<<(Mz*256)/1024, 256>>>(x);
    gates_gemm_mma<<<gemm_grid, 256, GEMM_SMEM>>>(bih_f0, bhh_f0, bih_r0, bhh_r0, 256, 1);
    lstm_recur_mma<<<2*NCD, 256, REC_SMEM>>>(Whh_f0, Whh_r0, outp, 0);

    // ---- layer 1 (K = 1024, 1-term W; A written by layer-0 recurrence) ----
    conv_W_f16<<<dim3((Gz*1024)/1024, 2), 256>>>(Wih_f1, Wih_r1, 1024);
    gates_gemm_mma<<<gemm_grid, 256, GEMM_SMEM>>>(bih_f1, bhh_f1, bih_r1, bhh_r1, 1024, 1);
    lstm_recur_mma<<<2*NCD, 256, REC_SMEM>>>(Whh_f1, Whh_r1, outp, 1);
}